// round 4
// baseline (speedup 1.0000x reference)
#include <cuda_runtime.h>

#define N    192
#define N4   (N/4)
#define N2   (N*N)
#define N3   (N*N*N)
#define C4   (N3/4)
#define SI4  (N2/4)
#define SJ4  (N/4)

#define DT      0.01f
#define HCELL   0.1f
#define GDT     (9.81f * 0.01f)
#define SCALE   (DT / HCELL)
#define ALPHA   (0.01f * 0.01f / (0.1f * 0.1f))
#define INVDIF  (1.0f / (1.0f + 6.0f * ALPHA))
#define INV2H   (1.0f / (2.0f * HCELL))
#define SIXTH   (1.0f / 6.0f)

__device__ float g_velA[3 * N3];
__device__ float g_velB[3 * N3];
__device__ float g_div [N3];
__device__ float g_pA  [N3];
__device__ float g_pB  [N3];

// ============================================================
// helper: k-neighbors across float4 boundary via warp shuffle.
// Call from ALL threads of the warp before any divergence.
// ============================================================
__device__ __forceinline__ void knb(const float4* base, int t, int k4,
                                    float cw, float cx,
                                    float& lm, float& rp) {
    lm = __shfl_up_sync(0xffffffffu, cw, 1);
    rp = __shfl_down_sync(0xffffffffu, cx, 1);
    int lane = threadIdx.x & 31;
    const float* s = (const float*)base;
    if (lane == 0  && k4 > 0)      lm = s[4 * t - 1];
    if (lane == 31 && k4 < N4 - 1) rp = s[4 * t + 4];
}

// ============================================================
// 1) gravity + advect, 4 cells per thread (float4 I/O, scalar gathers)
// ============================================================
__global__ void k_advect4(const float4* __restrict__ vin4, float4* __restrict__ vout4) {
    int t = blockIdx.x * blockDim.x + threadIdx.x;   // exact grid
    int k4 = t % N4;
    int j  = (t / N4) % N;
    int i  = t / SI4;

    float4 vx4 = vin4[t];
    float4 vy4 = vin4[t + C4];
    float4 vz4 = vin4[t + 2 * C4];
    const float* vin = (const float*)vin4;

    float vxa[4] = {vx4.x, vx4.y, vx4.z, vx4.w};
    float vya[4] = {vy4.x, vy4.y, vy4.z, vy4.w};
    float vza[4] = {vz4.x, vz4.y, vz4.z, vz4.w};
    float ox[4], oy[4], oz[4];

    #pragma unroll
    for (int q = 0; q < 4; q++) {
        int k = 4 * k4 + q;
        float vz = vza[q] - GDT;

        float px = fminf(fmaxf((float)i - vxa[q] * SCALE, 0.0f), (float)(N - 2));
        float py = fminf(fmaxf((float)j - vya[q] * SCALE, 0.0f), (float)(N - 2));
        float pz = fminf(fmaxf((float)k - vz     * SCALE, 0.0f), (float)(N - 2));

        int ix = (int)px, iy = (int)py, iz = (int)pz;
        float wx1 = px - (float)ix, wy1 = py - (float)iy, wz1 = pz - (float)iz;
        float wx0 = 1.0f - wx1,     wy0 = 1.0f - wy1,    wz0 = 1.0f - wz1;

        float w000 = wx0 * wy0 * wz0, w001 = wx0 * wy0 * wz1;
        float w010 = wx0 * wy1 * wz0, w011 = wx0 * wy1 * wz1;
        float w100 = wx1 * wy0 * wz0, w101 = wx1 * wy0 * wz1;
        float w110 = wx1 * wy1 * wz0, w111 = wx1 * wy1 * wz1;

        int b = (ix * N + iy) * N + iz;

        const float* f0 = vin;
        ox[q] = f0[b]          * w000 + f0[b + 1]          * w001
              + f0[b + N]      * w010 + f0[b + N + 1]      * w011
              + f0[b + N2]     * w100 + f0[b + N2 + 1]     * w101
              + f0[b + N2 + N] * w110 + f0[b + N2 + N + 1] * w111;
        const float* f1 = vin + N3;
        oy[q] = f1[b]          * w000 + f1[b + 1]          * w001
              + f1[b + N]      * w010 + f1[b + N + 1]      * w011
              + f1[b + N2]     * w100 + f1[b + N2 + 1]     * w101
              + f1[b + N2 + N] * w110 + f1[b + N2 + N + 1] * w111;
        const float* f2 = vin + 2 * N3;
        oz[q] = f2[b]          * w000 + f2[b + 1]          * w001
              + f2[b + N]      * w010 + f2[b + N + 1]      * w011
              + f2[b + N2]     * w100 + f2[b + N2 + 1]     * w101
              + f2[b + N2 + N] * w110 + f2[b + N2 + N + 1] * w111
              - GDT;                       // trilerp(vz - g dt) = trilerp(vz) - g dt
    }

    vout4[t]          = make_float4(ox[0], ox[1], ox[2], ox[3]);
    vout4[t + C4]     = make_float4(oy[0], oy[1], oy[2], oy[3]);
    vout4[t + 2 * C4] = make_float4(oz[0], oz[1], oz[2], oz[3]);
}

// ============================================================
// 2) one Jacobi diffusion sweep, all 3 components, float4 + shuffles
// ============================================================
__global__ void k_diffuse4(const float4* __restrict__ vin, float4* __restrict__ vout) {
    int t = blockIdx.x * blockDim.x + threadIdx.x;   // exact grid (3*C4 threads)
    int cell = t % C4;
    int k4 = cell % N4;
    int j  = (cell / N4) % N;
    int i  = cell / SI4;

    float4 c = vin[t];
    float lm, rp;
    knb(vin, t, k4, c.w, c.x, lm, rp);   // component boundaries guarded by k4 predicates

    if (i == 0 || i == N - 1 || j == 0 || j == N - 1) { vout[t] = c; return; }

    float4 a1 = vin[t + SI4], a2 = vin[t - SI4];
    float4 b1 = vin[t + SJ4], b2 = vin[t - SJ4];

    float4 o;
    o.x = (k4 == 0)
        ? c.x
        : (c.x + ALPHA * (a1.x + a2.x + b1.x + b2.x + lm  + c.y)) * INVDIF;
    o.y =   (c.y + ALPHA * (a1.y + a2.y + b1.y + b2.y + c.x + c.z)) * INVDIF;
    o.z =   (c.z + ALPHA * (a1.z + a2.z + b1.z + b2.z + c.y + c.w)) * INVDIF;
    o.w = (k4 == N4 - 1)
        ? c.w
        : (c.w + ALPHA * (a1.w + a2.w + b1.w + b2.w + c.z + rp )) * INVDIF;
    vout[t] = o;
}

// ============================================================
// 3) divergence + first pressure sweep fused (p1 = div/6)
// ============================================================
__global__ void k_div_p0(const float4* __restrict__ v,
                         float4* __restrict__ dv, float4* __restrict__ p) {
    int t = blockIdx.x * blockDim.x + threadIdx.x;
    int k4 = t % N4;
    int j  = (t / N4) % N;
    int i  = t / SI4;

    const float4* vz = v + 2 * C4;
    float4 zc = vz[t];
    float zl, zr;
    knb(vz, t, k4, zc.w, zc.x, zl, zr);

    float4 d = make_float4(0.f, 0.f, 0.f, 0.f);
    if (!(i == 0 || i == N - 1 || j == 0 || j == N - 1)) {
        const float4* vx = v;
        const float4* vy = v + C4;
        float4 xa = vx[t + SI4], xb = vx[t - SI4];
        float4 ya = vy[t + SJ4], yb = vy[t - SJ4];

        if (k4 != 0)
            d.x = ((xa.x - xb.x) + (ya.x - yb.x) + (zc.y - zl))   * INV2H;
        d.y =     ((xa.y - xb.y) + (ya.y - yb.y) + (zc.z - zc.x)) * INV2H;
        d.z =     ((xa.z - xb.z) + (ya.z - yb.z) + (zc.w - zc.y)) * INV2H;
        if (k4 != N4 - 1)
            d.w = ((xa.w - xb.w) + (ya.w - yb.w) + (zr   - zc.z)) * INV2H;
    }
    dv[t] = d;
    p[t] = make_float4(d.x * SIXTH, d.y * SIXTH, d.z * SIXTH, d.w * SIXTH);
}

// ============================================================
// 4) generic pressure Jacobi sweep
// ============================================================
__global__ void k_pressure4(const float4* __restrict__ dv,
                            const float4* __restrict__ pin,
                            float4* __restrict__ pout) {
    int t = blockIdx.x * blockDim.x + threadIdx.x;
    int k4 = t % N4;
    int j  = (t / N4) % N;
    int i  = t / SI4;

    float4 c = pin[t];
    float lm, rp;
    knb(pin, t, k4, c.w, c.x, lm, rp);

    if (i == 0 || i == N - 1 || j == 0 || j == N - 1) {
        pout[t] = make_float4(0.f, 0.f, 0.f, 0.f);
        return;
    }
    float4 a1 = pin[t + SI4], a2 = pin[t - SI4];
    float4 b1 = pin[t + SJ4], b2 = pin[t - SJ4];
    float4 d  = dv[t];

    float4 o;
    o.x = (k4 == 0)      ? 0.0f
        : (d.x + a1.x + a2.x + b1.x + b2.x + lm  + c.y) * SIXTH;
    o.y =  (d.y + a1.y + a2.y + b1.y + b2.y + c.x + c.z) * SIXTH;
    o.z =  (d.z + a1.z + a2.z + b1.z + b2.z + c.y + c.w) * SIXTH;
    o.w = (k4 == N4 - 1) ? 0.0f
        : (d.w + a1.w + a2.w + b1.w + b2.w + c.z + rp ) * SIXTH;
    pout[t] = o;
}

// ============================================================
// 5) subtract pressure gradient -> output
// ============================================================
__global__ void k_project4(const float4* __restrict__ v,
                           const float4* __restrict__ p,
                           float4* __restrict__ out) {
    int t = blockIdx.x * blockDim.x + threadIdx.x;
    int k4 = t % N4;
    int j  = (t / N4) % N;
    int i  = t / SI4;

    float4 pz = p[t];
    float pl, pr;
    knb(p, t, k4, pz.w, pz.x, pl, pr);

    float4 v0 = v[t], v1 = v[t + C4], v2 = v[t + 2 * C4];

    if (!(i == 0 || i == N - 1 || j == 0 || j == N - 1)) {
        float4 pa = p[t + SI4], pb = p[t - SI4];
        float4 pc = p[t + SJ4], pd = p[t - SJ4];

        if (k4 != 0) {
            v0.x -= (pa.x - pb.x) * INV2H;
            v1.x -= (pc.x - pd.x) * INV2H;
            v2.x -= (pz.y - pl)   * INV2H;
        }
        v0.y -= (pa.y - pb.y) * INV2H;
        v1.y -= (pc.y - pd.y) * INV2H;
        v2.y -= (pz.z - pz.x) * INV2H;

        v0.z -= (pa.z - pb.z) * INV2H;
        v1.z -= (pc.z - pd.z) * INV2H;
        v2.z -= (pz.w - pz.y) * INV2H;

        if (k4 != N4 - 1) {
            v0.w -= (pa.w - pb.w) * INV2H;
            v1.w -= (pc.w - pd.w) * INV2H;
            v2.w -= (pr   - pz.z) * INV2H;
        }
    }
    out[t]          = v0;
    out[t + C4]     = v1;
    out[t + 2 * C4] = v2;
}

// ============================================================
// host launcher (graph-capturable: kernel launches only)
// ============================================================
extern "C" void kernel_launch(void* const* d_in, const int* in_sizes, int n_in,
                              void* d_out, int out_size) {
    const float* vin = (const float*)d_in[0];
    float* out = (float*)d_out;

    float *velA, *velB, *dv, *pA, *pB;
    cudaGetSymbolAddress((void**)&velA, g_velA);
    cudaGetSymbolAddress((void**)&velB, g_velB);
    cudaGetSymbolAddress((void**)&dv,   g_div);
    cudaGetSymbolAddress((void**)&pA,   g_pA);
    cudaGetSymbolAddress((void**)&pB,   g_pB);

    const int T = 256;
    const int blocksC4 = C4 / T;          // exact
    const int blocksV4 = (3 * C4) / T;    // exact

    // gravity + advect (vectorized)
    k_advect4<<<blocksC4, T>>>((const float4*)vin, (float4*)velA);

    // 5 Jacobi diffusion sweeps, all components per sweep (ping-pong)
    float* a = velA; float* b = velB;
    for (int s = 0; s < 5; s++) {
        k_diffuse4<<<blocksV4, T>>>((const float4*)a, (float4*)b);
        float* tmp = a; a = b; b = tmp;
    }

    // divergence + first pressure sweep fused
    k_div_p0<<<blocksC4, T>>>((const float4*)a, (float4*)dv, (float4*)pA);

    // 19 remaining pressure Jacobi sweeps
    float* pa = pA; float* pb = pB;
    for (int s = 0; s < 19; s++) {
        k_pressure4<<<blocksC4, T>>>((const float4*)dv, (const float4*)pa, (float4*)pb);
        float* tmp = pa; pa = pb; pb = tmp;
    }

    // gradient subtract -> output
    k_project4<<<blocksC4, T>>>((const float4*)a, (const float4*)pa, (float4*)out);
}

// round 5
// speedup vs baseline: 1.1230x; 1.1230x over previous
#include <cuda_runtime.h>

#define N    192
#define N4   (N/4)          // 48
#define N2   (N*N)
#define N3   (N*N*N)
#define C4   (N3/4)
#define SI4  (N2/4)         // 9216
#define H4   (C4/2)         // paired-i threads per scalar field

#define DT      0.01f
#define HCELL   0.1f
#define GDT     (9.81f * 0.01f)
#define SCALE   (DT / HCELL)
#define ALPHA   (0.01f * 0.01f / (0.1f * 0.1f))
#define INVDIF  (1.0f / (1.0f + 6.0f * ALPHA))
#define INV2H   (1.0f / (2.0f * HCELL))
#define SIXTH   (1.0f / 6.0f)

__device__ float g_velA[3 * N3];
__device__ float g_velB[3 * N3];
__device__ float g_div [N3];
__device__ float g_pA  [N3];
__device__ float g_pB  [N3];

// ============================================================
// helper: k-neighbors across float4 boundary via warp shuffle.
// Call from ALL threads of the warp before any divergence.
// Edge lanes / row-straddles fall back to a scalar load; values
// are only USED under k4>0 / k4<N4-1 predicates.
// ============================================================
__device__ __forceinline__ void knb(const float4* base, int t, int k4,
                                    float cw, float cx,
                                    float& lm, float& rp) {
    lm = __shfl_up_sync(0xffffffffu, cw, 1);
    rp = __shfl_down_sync(0xffffffffu, cx, 1);
    int lane = threadIdx.x & 31;
    const float* s = (const float*)base;
    if (lane == 0  && k4 > 0)      lm = s[4 * t - 1];
    if (lane == 31 && k4 < N4 - 1) rp = s[4 * t + 4];
}

// ============================================================
// 1) gravity + semi-Lagrangian advection (scalar — proven fastest)
// ============================================================
__global__ void k_advect(const float* __restrict__ vin, float* __restrict__ vout) {
    int idx = blockIdx.x * blockDim.x + threadIdx.x;
    if (idx >= N3) return;
    int k = idx % N;
    int j = (idx / N) % N;
    int i = idx / N2;

    float vx = vin[idx];
    float vy = vin[N3 + idx];
    float vz = vin[2 * N3 + idx] - GDT;

    float px = fminf(fmaxf((float)i - vx * SCALE, 0.0f), (float)(N - 2));
    float py = fminf(fmaxf((float)j - vy * SCALE, 0.0f), (float)(N - 2));
    float pz = fminf(fmaxf((float)k - vz * SCALE, 0.0f), (float)(N - 2));

    int ix = (int)px, iy = (int)py, iz = (int)pz;
    float wx1 = px - (float)ix, wy1 = py - (float)iy, wz1 = pz - (float)iz;
    float wx0 = 1.0f - wx1,     wy0 = 1.0f - wy1,    wz0 = 1.0f - wz1;

    float w000 = wx0 * wy0 * wz0, w001 = wx0 * wy0 * wz1;
    float w010 = wx0 * wy1 * wz0, w011 = wx0 * wy1 * wz1;
    float w100 = wx1 * wy0 * wz0, w101 = wx1 * wy0 * wz1;
    float w110 = wx1 * wy1 * wz0, w111 = wx1 * wy1 * wz1;

    int b = (ix * N + iy) * N + iz;

    #pragma unroll
    for (int c = 0; c < 3; c++) {
        const float* f = vin + c * N3;
        float v = f[b]          * w000 + f[b + 1]          * w001
                + f[b + N]      * w010 + f[b + N + 1]      * w011
                + f[b + N2]     * w100 + f[b + N2 + 1]     * w101
                + f[b + N2 + N] * w110 + f[b + N2 + N + 1] * w111;
        if (c == 2) v -= GDT;
        vout[c * N3 + idx] = v;
    }
}

// ============================================================
// 2) diffusion sweep: 2 i-rows per thread, all 3 components
//    grid = 3 * H4 threads (exact)
// ============================================================
__global__ void k_diffuse2(const float4* __restrict__ vin, float4* __restrict__ vout) {
    int t2 = blockIdx.x * blockDim.x + threadIdx.x;
    int comp = t2 / H4;
    int r    = t2 % H4;
    int k4 = r % N4;
    int j  = (r / N4) % N;
    int i0 = 2 * (r / (N4 * N));          // even row; i1 = i0+1

    int t0 = comp * C4 + i0 * SI4 + j * N4 + k4;
    int t1 = t0 + SI4;

    float4 c0 = vin[t0];
    float4 c1 = vin[t1];
    float lm0, rp0, lm1, rp1;
    knb(vin, t0, k4, c0.w, c0.x, lm0, rp0);
    knb(vin, t1, k4, c1.w, c1.x, lm1, rp1);

    if (j == 0 || j == N - 1) {           // j-boundary: pass through
        vout[t0] = c0; vout[t1] = c1;
        return;
    }

    float4 b10 = vin[t0 + N4], b20 = vin[t0 - N4];
    float4 b11 = vin[t1 + N4], b21 = vin[t1 - N4];

    float4 o0, o1;
    if (i0 == 0) {                        // i=0 boundary row: copy
        o0 = c0;
    } else {
        float4 pm = vin[t0 - SI4];        // i0-1 ; i0+1 neighbor is c1
        o0.x = (k4 == 0) ? c0.x
             : (c0.x + ALPHA * (pm.x + c1.x + b10.x + b20.x + lm0 + c0.y)) * INVDIF;
        o0.y =  (c0.y + ALPHA * (pm.y + c1.y + b10.y + b20.y + c0.x + c0.z)) * INVDIF;
        o0.z =  (c0.z + ALPHA * (pm.z + c1.z + b10.z + b20.z + c0.y + c0.w)) * INVDIF;
        o0.w = (k4 == N4 - 1) ? c0.w
             : (c0.w + ALPHA * (pm.w + c1.w + b10.w + b20.w + c0.z + rp0)) * INVDIF;
    }
    if (i0 + 2 == N) {                    // i1 = N-1 boundary row: copy
        o1 = c1;
    } else {
        float4 pp = vin[t1 + SI4];        // i1+1 ; i1-1 neighbor is c0
        o1.x = (k4 == 0) ? c1.x
             : (c1.x + ALPHA * (c0.x + pp.x + b11.x + b21.x + lm1 + c1.y)) * INVDIF;
        o1.y =  (c1.y + ALPHA * (c0.y + pp.y + b11.y + b21.y + c1.x + c1.z)) * INVDIF;
        o1.z =  (c1.z + ALPHA * (c0.z + pp.z + b11.z + b21.z + c1.y + c1.w)) * INVDIF;
        o1.w = (k4 == N4 - 1) ? c1.w
             : (c1.w + ALPHA * (c0.w + pp.w + b11.w + b21.w + c1.z + rp1)) * INVDIF;
    }
    vout[t0] = o0;
    vout[t1] = o1;
}

// ============================================================
// 3) divergence + first pressure sweep fused (p1 = div/6)
// ============================================================
__global__ void k_div_p0(const float4* __restrict__ v,
                         float4* __restrict__ dv, float4* __restrict__ p) {
    int t = blockIdx.x * blockDim.x + threadIdx.x;
    int k4 = t % N4;
    int j  = (t / N4) % N;
    int i  = t / SI4;

    const float4* vz = v + 2 * C4;
    float4 zc = vz[t];
    float zl, zr;
    knb(vz, t, k4, zc.w, zc.x, zl, zr);

    float4 d = make_float4(0.f, 0.f, 0.f, 0.f);
    if (!(i == 0 || i == N - 1 || j == 0 || j == N - 1)) {
        const float4* vx = v;
        const float4* vy = v + C4;
        float4 xa = vx[t + SI4], xb = vx[t - SI4];
        float4 ya = vy[t + N4],  yb = vy[t - N4];

        if (k4 != 0)
            d.x = ((xa.x - xb.x) + (ya.x - yb.x) + (zc.y - zl))   * INV2H;
        d.y =     ((xa.y - xb.y) + (ya.y - yb.y) + (zc.z - zc.x)) * INV2H;
        d.z =     ((xa.z - xb.z) + (ya.z - yb.z) + (zc.w - zc.y)) * INV2H;
        if (k4 != N4 - 1)
            d.w = ((xa.w - xb.w) + (ya.w - yb.w) + (zr   - zc.z)) * INV2H;
    }
    dv[t] = d;
    p[t] = make_float4(d.x * SIXTH, d.y * SIXTH, d.z * SIXTH, d.w * SIXTH);
}

// ============================================================
// 4) pressure Jacobi sweep: 2 i-rows per thread (grid = H4, exact)
// ============================================================
__global__ void k_pressure2(const float4* __restrict__ dv,
                            const float4* __restrict__ pin,
                            float4* __restrict__ pout) {
    int t2 = blockIdx.x * blockDim.x + threadIdx.x;
    int k4 = t2 % N4;
    int j  = (t2 / N4) % N;
    int i0 = 2 * (t2 / (N4 * N));

    int t0 = i0 * SI4 + j * N4 + k4;
    int t1 = t0 + SI4;

    float4 c0 = pin[t0];
    float4 c1 = pin[t1];
    float lm0, rp0, lm1, rp1;
    knb(pin, t0, k4, c0.w, c0.x, lm0, rp0);
    knb(pin, t1, k4, c1.w, c1.x, lm1, rp1);

    const float4 Z = make_float4(0.f, 0.f, 0.f, 0.f);
    if (j == 0 || j == N - 1) {
        pout[t0] = Z; pout[t1] = Z;
        return;
    }

    float4 b10 = pin[t0 + N4], b20 = pin[t0 - N4];
    float4 b11 = pin[t1 + N4], b21 = pin[t1 - N4];

    float4 o0 = Z, o1 = Z;
    if (i0 != 0) {
        float4 pm = pin[t0 - SI4];
        float4 d0 = dv[t0];
        o0.x = (k4 == 0) ? 0.f
             : (d0.x + pm.x + c1.x + b10.x + b20.x + lm0 + c0.y) * SIXTH;
        o0.y =  (d0.y + pm.y + c1.y + b10.y + b20.y + c0.x + c0.z) * SIXTH;
        o0.z =  (d0.z + pm.z + c1.z + b10.z + b20.z + c0.y + c0.w) * SIXTH;
        o0.w = (k4 == N4 - 1) ? 0.f
             : (d0.w + pm.w + c1.w + b10.w + b20.w + c0.z + rp0) * SIXTH;
    }
    if (i0 + 2 != N) {
        float4 pp = pin[t1 + SI4];
        float4 d1 = dv[t1];
        o1.x = (k4 == 0) ? 0.f
             : (d1.x + c0.x + pp.x + b11.x + b21.x + lm1 + c1.y) * SIXTH;
        o1.y =  (d1.y + c0.y + pp.y + b11.y + b21.y + c1.x + c1.z) * SIXTH;
        o1.z =  (d1.z + c0.z + pp.z + b11.z + b21.z + c1.y + c1.w) * SIXTH;
        o1.w = (k4 == N4 - 1) ? 0.f
             : (d1.w + c0.w + pp.w + b11.w + b21.w + c1.z + rp1) * SIXTH;
    }
    pout[t0] = o0;
    pout[t1] = o1;
}

// ============================================================
// 5) subtract pressure gradient -> output
// ============================================================
__global__ void k_project4(const float4* __restrict__ v,
                           const float4* __restrict__ p,
                           float4* __restrict__ out) {
    int t = blockIdx.x * blockDim.x + threadIdx.x;
    int k4 = t % N4;
    int j  = (t / N4) % N;
    int i  = t / SI4;

    float4 pz = p[t];
    float pl, pr;
    knb(p, t, k4, pz.w, pz.x, pl, pr);

    float4 v0 = v[t], v1 = v[t + C4], v2 = v[t + 2 * C4];

    if (!(i == 0 || i == N - 1 || j == 0 || j == N - 1)) {
        float4 pa = p[t + SI4], pb = p[t - SI4];
        float4 pc = p[t + N4],  pd = p[t - N4];

        if (k4 != 0) {
            v0.x -= (pa.x - pb.x) * INV2H;
            v1.x -= (pc.x - pd.x) * INV2H;
            v2.x -= (pz.y - pl)   * INV2H;
        }
        v0.y -= (pa.y - pb.y) * INV2H;
        v1.y -= (pc.y - pd.y) * INV2H;
        v2.y -= (pz.z - pz.x) * INV2H;

        v0.z -= (pa.z - pb.z) * INV2H;
        v1.z -= (pc.z - pd.z) * INV2H;
        v2.z -= (pz.w - pz.y) * INV2H;

        if (k4 != N4 - 1) {
            v0.w -= (pa.w - pb.w) * INV2H;
            v1.w -= (pc.w - pd.w) * INV2H;
            v2.w -= (pr   - pz.z) * INV2H;
        }
    }
    out[t]          = v0;
    out[t + C4]     = v1;
    out[t + 2 * C4] = v2;
}

// ============================================================
// host launcher (graph-capturable: kernel launches only)
// ============================================================
extern "C" void kernel_launch(void* const* d_in, const int* in_sizes, int n_in,
                              void* d_out, int out_size) {
    const float* vin = (const float*)d_in[0];
    float* out = (float*)d_out;

    float *velA, *velB, *dv, *pA, *pB;
    cudaGetSymbolAddress((void**)&velA, g_velA);
    cudaGetSymbolAddress((void**)&velB, g_velB);
    cudaGetSymbolAddress((void**)&dv,   g_div);
    cudaGetSymbolAddress((void**)&pA,   g_pA);
    cudaGetSymbolAddress((void**)&pB,   g_pB);

    const int T = 256;
    const int blocksCell = (N3 + T - 1) / T;   // scalar advect
    const int blocksC4   = C4 / T;             // exact
    const int blocksH4   = H4 / T;             // exact (paired pressure)
    const int blocksD2   = (3 * H4) / T;       // exact (paired diffuse)

    // gravity + advect (scalar — best measured)
    k_advect<<<blocksCell, T>>>(vin, velA);

    // 5 diffusion sweeps, 2 rows/thread, all components (ping-pong)
    float* a = velA; float* b = velB;
    for (int s = 0; s < 5; s++) {
        k_diffuse2<<<blocksD2, T>>>((const float4*)a, (float4*)b);
        float* tmp = a; a = b; b = tmp;
    }

    // divergence + first pressure sweep fused
    k_div_p0<<<blocksC4, T>>>((const float4*)a, (float4*)dv, (float4*)pA);

    // 19 remaining pressure sweeps, 2 rows/thread
    float* pa = pA; float* pb = pB;
    for (int s = 0; s < 19; s++) {
        k_pressure2<<<blocksH4, T>>>((const float4*)dv, (const float4*)pa, (float4*)pb);
        float* tmp = pa; pa = pb; pb = tmp;
    }

    // gradient subtract -> output
    k_project4<<<blocksC4, T>>>((const float4*)a, (const float4*)pa, (float4*)out);
}